// round 2
// baseline (speedup 1.0000x reference)
#include <cuda_runtime.h>
#include <math.h>

// Problem constants
#define BB   4
#define TT   2048
#define CC   1024
#define HH   16
#define DD   64
#define MTOT (BB*TT)          // 8192
#define NQKV (3*CC)           // 3072

// Scratch in device globals (no allocations allowed)
__device__ float g_Q[(size_t)BB*HH*TT*DD];
__device__ float g_K[(size_t)BB*HH*TT*DD];
__device__ float g_V[(size_t)BB*HH*TT*DD];
__device__ float g_O[(size_t)BB*TT*CC];

// ---------------------------------------------------------------------------
// SGEMM (NT): C[m,n] = sum_k A[m,k] * W[n,k]
// 128x128 block tile, K-tile 8, 256 threads, 8x8 per thread (split 4+4).
// EPI==0 : QKV epilogue -> scatter into g_Q/g_K/g_V ([B,H,T,D]), Q scaled.
// EPI==1 : out-projection, A is ignored and g_O used; result -> Cout.
// ---------------------------------------------------------------------------
template<int EPI>
__global__ __launch_bounds__(256)
void sgemm_nt(const float* __restrict__ A, const float* __restrict__ W,
              float* __restrict__ Cout, int Mdim, int Ndim, int Kdim)
{
    __shared__ float As[8][128];
    __shared__ float Bs[8][128];

    const float* Abase = (EPI == 1) ? (const float*)g_O : A;

    const int tid = threadIdx.x;
    const int bm = blockIdx.y, bn = blockIdx.x;
    const int lr = tid >> 1;           // 0..127
    const int lc = (tid & 1) * 4;      // 0 or 4
    const float* Ap = Abase + (size_t)(bm * 128 + lr) * Kdim + lc;
    const float* Bp = W     + (size_t)(bn * 128 + lr) * Kdim + lc;
    const int tx = tid & 15, ty = tid >> 4;

    float acc[8][8];
#pragma unroll
    for (int i = 0; i < 8; i++)
#pragma unroll
        for (int j = 0; j < 8; j++) acc[i][j] = 0.f;

    for (int k0 = 0; k0 < Kdim; k0 += 8) {
        float4 a4 = *(const float4*)(Ap + k0);
        float4 b4 = *(const float4*)(Bp + k0);
        __syncthreads();
        As[lc + 0][lr] = a4.x; As[lc + 1][lr] = a4.y;
        As[lc + 2][lr] = a4.z; As[lc + 3][lr] = a4.w;
        Bs[lc + 0][lr] = b4.x; Bs[lc + 1][lr] = b4.y;
        Bs[lc + 2][lr] = b4.z; Bs[lc + 3][lr] = b4.w;
        __syncthreads();
#pragma unroll
        for (int kk = 0; kk < 8; kk++) {
            float af[8], bf[8];
            *(float4*)(af)     = *(const float4*)(&As[kk][ty * 4]);
            *(float4*)(af + 4) = *(const float4*)(&As[kk][64 + ty * 4]);
            *(float4*)(bf)     = *(const float4*)(&Bs[kk][tx * 4]);
            *(float4*)(bf + 4) = *(const float4*)(&Bs[kk][64 + tx * 4]);
#pragma unroll
            for (int i = 0; i < 8; i++)
#pragma unroll
                for (int j = 0; j < 8; j++)
                    acc[i][j] += af[i] * bf[j];
        }
    }

#pragma unroll
    for (int i = 0; i < 8; i++) {
        int m = bm * 128 + ((i < 4) ? (ty * 4 + i) : (64 + ty * 4 + i - 4));
#pragma unroll
        for (int j = 0; j < 8; j++) {
            int n = bn * 128 + ((j < 4) ? (tx * 4 + j) : (64 + tx * 4 + j - 4));
            float v = acc[i][j];
            if (EPI == 0) {
                int which = n >> 10;         // 0=q,1=k,2=v
                int c = n & 1023;
                int h = c >> 6, d = c & 63;
                int b = m >> 11, t = m & 2047;
                size_t idx = (((size_t)(b * HH + h)) * TT + t) * DD + d;
                if (which == 0)      g_Q[idx] = v * 0.125f;   // 1/sqrt(64)
                else if (which == 1) g_K[idx] = v;
                else                 g_V[idx] = v;
            } else {
                Cout[(size_t)m * Ndim + n] = v;
            }
        }
    }
}

// ---------------------------------------------------------------------------
// Flash attention (causal), fp32. One block per (q-tile of 64, head, batch).
// 256 threads: 64 rows x 4 threads/row, 16 cols (or dims) per thread.
// smem tiles with stride 68 floats: conflict-free and float4-aligned.
// ---------------------------------------------------------------------------
#define LDS_STRIDE 68
#define SMEM_FLOATS (4 * 64 * LDS_STRIDE)

__global__ __launch_bounds__(256)
void flash_attn_kernel()
{
    extern __shared__ float sm[];
    float* Qs = sm;                       // [64][68]   Qs[r][d]
    float* Kt = sm + 64 * LDS_STRIDE;     // [64][68]   Kt[d][c] (transposed)
    float* Vs = sm + 2 * 64 * LDS_STRIDE; // [64][68]   Vs[c][d]
    float* Ps = sm + 3 * 64 * LDS_STRIDE; // [64][68]   Ps[r][c]

    const int b = blockIdx.z, h = blockIdx.y, qb = blockIdx.x;
    const int tid = threadIdx.x;
    const size_t headbase = ((size_t)(b * HH + h)) * TT * DD;
    const float* Qg = g_Q + headbase + (size_t)qb * 64 * DD;
    const float* Kg = g_K + headbase;
    const float* Vg = g_V + headbase;

    // load Q tile (float4, coalesced)
#pragma unroll
    for (int i = 0; i < 4; i++) {
        int idx = tid + i * 256;          // 0..1023 float4 index
        int r = idx >> 4;
        int c4 = (idx & 15) * 4;
        *(float4*)&Qs[r * LDS_STRIDE + c4] = *(const float4*)&Qg[r * 64 + c4];
    }

    const int r  = tid >> 2;        // query row 0..63
    const int cq = (tid & 3) * 16;  // this thread's 16-col segment

    float m_i = -INFINITY, l_i = 0.f;
    float o[16];
#pragma unroll
    for (int i = 0; i < 16; i++) o[i] = 0.f;

    for (int j = 0; j <= qb; j++) {
        __syncthreads();   // previous iteration done reading Kt/Vs/Ps
        const float* Kj = Kg + (size_t)j * 64 * DD;
        const float* Vj = Vg + (size_t)j * 64 * DD;
        // K tile, transposed store Kt[d][c]
#pragma unroll
        for (int i = 0; i < 16; i++) {
            int idx = tid + i * 256;      // 0..4095
            int c = idx >> 6, d = idx & 63;
            Kt[d * LDS_STRIDE + c] = Kj[idx];
        }
        // V tile, straight float4 copy
#pragma unroll
        for (int i = 0; i < 4; i++) {
            int idx = tid + i * 256;
            int rr = idx >> 4;
            int c4 = (idx & 15) * 4;
            *(float4*)&Vs[rr * LDS_STRIDE + c4] = *(const float4*)&Vj[rr * 64 + c4];
        }
        __syncthreads();

        // S = Q K^T for this thread's 16 columns
        float s[16];
#pragma unroll
        for (int i = 0; i < 16; i++) s[i] = 0.f;
#pragma unroll 8
        for (int d = 0; d < 64; d++) {
            float qv = Qs[r * LDS_STRIDE + d];
            const float* kr = &Kt[d * LDS_STRIDE + cq];
#pragma unroll
            for (int cc = 0; cc < 16; cc += 4) {
                float4 k4 = *(const float4*)(kr + cc);
                s[cc + 0] += qv * k4.x;
                s[cc + 1] += qv * k4.y;
                s[cc + 2] += qv * k4.z;
                s[cc + 3] += qv * k4.w;
            }
        }
        // causal mask on the diagonal block
        if (j == qb) {
#pragma unroll
            for (int cc = 0; cc < 16; cc++)
                if (cq + cc > r) s[cc] = -INFINITY;
        }
        // online softmax
        float mloc = s[0];
#pragma unroll
        for (int cc = 1; cc < 16; cc++) mloc = fmaxf(mloc, s[cc]);
        mloc = fmaxf(mloc, __shfl_xor_sync(0xffffffffu, mloc, 1));
        mloc = fmaxf(mloc, __shfl_xor_sync(0xffffffffu, mloc, 2));
        float m_new = fmaxf(m_i, mloc);
        float alpha = __expf(m_i - m_new);
        float psum = 0.f;
#pragma unroll
        for (int cc = 0; cc < 16; cc++) {
            float p = __expf(s[cc] - m_new);
            s[cc] = p;
            psum += p;
        }
        psum += __shfl_xor_sync(0xffffffffu, psum, 1);
        psum += __shfl_xor_sync(0xffffffffu, psum, 2);
        l_i = alpha * l_i + psum;
        m_i = m_new;
#pragma unroll
        for (int cc = 0; cc < 16; cc += 4) {
            float4 p4 = make_float4(s[cc], s[cc + 1], s[cc + 2], s[cc + 3]);
            *(float4*)&Ps[r * LDS_STRIDE + cq + cc] = p4;
        }
#pragma unroll
        for (int dd = 0; dd < 16; dd++) o[dd] *= alpha;
        __syncthreads();

        // O += P V  (this thread owns dims cq..cq+15 of row r)
#pragma unroll 8
        for (int c = 0; c < 64; c++) {
            float pv = Ps[r * LDS_STRIDE + c];
            const float* vr = &Vs[c * LDS_STRIDE + cq];
#pragma unroll
            for (int dd = 0; dd < 16; dd += 4) {
                float4 v4 = *(const float4*)(vr + dd);
                o[dd + 0] += pv * v4.x;
                o[dd + 1] += pv * v4.y;
                o[dd + 2] += pv * v4.z;
                o[dd + 3] += pv * v4.w;
            }
        }
    }

    const float inv = 1.f / l_i;
    float* Og = g_O + ((size_t)(b * TT + qb * 64 + r)) * CC + h * DD + cq;
#pragma unroll
    for (int dd = 0; dd < 16; dd += 4) {
        float4 r4 = make_float4(o[dd] * inv, o[dd + 1] * inv,
                                o[dd + 2] * inv, o[dd + 3] * inv);
        *(float4*)(Og + dd) = r4;
    }
}

// ---------------------------------------------------------------------------
extern "C" void kernel_launch(void* const* d_in, const int* in_sizes, int n_in,
                              void* d_out, int out_size)
{
    const float* x     = (const float*)d_in[0];
    // d_in[1] = mask (bool) — causal, applied analytically
    const float* w_qkv = (const float*)d_in[2];
    const float* w_out = (const float*)d_in[3];
    float* out = (float*)d_out;

    // 1) QKV projection -> g_Q (scaled), g_K, g_V
    {
        dim3 grid(NQKV / 128, MTOT / 128);   // (24, 64)
        sgemm_nt<0><<<grid, 256>>>(x, w_qkv, nullptr, MTOT, NQKV, CC);
    }
    // 2) causal flash attention -> g_O
    {
        cudaFuncSetAttribute(flash_attn_kernel,
                             cudaFuncAttributeMaxDynamicSharedMemorySize,
                             SMEM_FLOATS * (int)sizeof(float));
        dim3 grid(TT / 64, HH, BB);          // (32, 16, 4)
        flash_attn_kernel<<<grid, 256, SMEM_FLOATS * sizeof(float)>>>();
    }
    // 3) output projection -> d_out
    {
        dim3 grid(CC / 128, MTOT / 128);     // (8, 64)
        sgemm_nt<1><<<grid, 256>>>(nullptr, w_out, out, MTOT, CC, CC);
    }
}

// round 4
// speedup vs baseline: 2.4028x; 2.4028x over previous
#include <cuda_runtime.h>
#include <math.h>

// Problem constants
#define BB   4
#define TT   2048
#define CC   1024
#define HH   16
#define DD   64
#define MTOT (BB*TT)          // 8192
#define NQKV (3*CC)           // 3072

typedef unsigned long long u64;

// Scratch in device globals (no allocations allowed)
__device__ float g_Q[(size_t)BB*HH*TT*DD];
__device__ float g_K[(size_t)BB*HH*TT*DD];
__device__ float g_V[(size_t)BB*HH*TT*DD];
__device__ float g_O[(size_t)BB*TT*CC];

// ---------------------------------------------------------------------------
// Packed f32x2 helpers (Blackwell: fma.rn.f32x2 — 2 FMAs per fma-pipe slot)
// ---------------------------------------------------------------------------
__device__ __forceinline__ u64 pk2d(float x) {               // {x, x}
    u64 r; unsigned u = __float_as_uint(x);
    asm("mov.b64 %0, {%1, %1};" : "=l"(r) : "r"(u));
    return r;
}
__device__ __forceinline__ void fma2(u64& d, u64 a, u64 b) {
    asm("fma.rn.f32x2 %0, %1, %2, %0;" : "+l"(d) : "l"(a), "l"(b));
}
__device__ __forceinline__ void mul2(u64& d, u64 a) {
    asm("mul.rn.f32x2 %0, %0, %1;" : "+l"(d) : "l"(a));
}
__device__ __forceinline__ void up2(u64 v, float& x, float& y) {
    unsigned a, b;
    asm("mov.b64 {%0, %1}, %2;" : "=r"(a), "=r"(b) : "l"(v));
    x = __uint_as_float(a); y = __uint_as_float(b);
}

// ---------------------------------------------------------------------------
// SGEMM (NT): C[m,n] = sum_k A[m,k] * W[n,k]
// 128x128 tile, K-tile 16, double-buffered smem, 256 threads,
// 8x8 per thread computed as 8x4 packed f32x2 accumulators.
// EPI==0 : QKV epilogue -> scatter into g_Q (scaled) /g_K/g_V  [B,H,T,D]
// EPI==1 : out projection, A := g_O, result -> Cout
// ---------------------------------------------------------------------------
template<int EPI>
__global__ __launch_bounds__(256)
void sgemm_nt(const float* __restrict__ A, const float* __restrict__ W,
              float* __restrict__ Cout, int Kdim, int Ndim)
{
    __shared__ float As[2][16][128];   // [buf][k][m]
    __shared__ float Bs[2][16][128];   // [buf][k][n]

    const float* Abase = (EPI == 1) ? (const float*)g_O : A;

    const int tid = threadIdx.x;
    const int bm = blockIdx.y, bn = blockIdx.x;
    const int lr = tid >> 1;            // 0..127 (tile row)
    const int lc = (tid & 1) * 8;       // 0 or 8 (k offset)
    const float* Ap = Abase + (size_t)(bm * 128 + lr) * Kdim + lc;
    const float* Bp = W     + (size_t)(bn * 128 + lr) * Kdim + lc;
    const int tx = tid & 15, ty = tid >> 4;

    u64 acc[8][4];
#pragma unroll
    for (int i = 0; i < 8; i++)
#pragma unroll
        for (int j = 0; j < 4; j++) acc[i][j] = 0ull;

    // Prologue: load k-tile 0 into buffer 0
    float4 a0 = *(const float4*)(Ap);
    float4 a1 = *(const float4*)(Ap + 4);
    float4 b0 = *(const float4*)(Bp);
    float4 b1 = *(const float4*)(Bp + 4);
    As[0][lc + 0][lr] = a0.x; As[0][lc + 1][lr] = a0.y;
    As[0][lc + 2][lr] = a0.z; As[0][lc + 3][lr] = a0.w;
    As[0][lc + 4][lr] = a1.x; As[0][lc + 5][lr] = a1.y;
    As[0][lc + 6][lr] = a1.z; As[0][lc + 7][lr] = a1.w;
    Bs[0][lc + 0][lr] = b0.x; Bs[0][lc + 1][lr] = b0.y;
    Bs[0][lc + 2][lr] = b0.z; Bs[0][lc + 3][lr] = b0.w;
    Bs[0][lc + 4][lr] = b1.x; Bs[0][lc + 5][lr] = b1.y;
    Bs[0][lc + 6][lr] = b1.z; Bs[0][lc + 7][lr] = b1.w;
    __syncthreads();

    const int nk = Kdim >> 4;
    int cur = 0;

    for (int kt = 0; kt < nk; kt++) {
        float4 na0, na1, nb0, nb1;
        const bool more = (kt + 1 < nk);
        if (more) {
            const float* Ap2 = Ap + (size_t)(kt + 1) * 16;
            const float* Bp2 = Bp + (size_t)(kt + 1) * 16;
            na0 = *(const float4*)(Ap2);
            na1 = *(const float4*)(Ap2 + 4);
            nb0 = *(const float4*)(Bp2);
            nb1 = *(const float4*)(Bp2 + 4);
        }
#pragma unroll
        for (int kk = 0; kk < 16; kk++) {
            float4 afl = *(const float4*)(&As[cur][kk][ty * 4]);
            float4 afh = *(const float4*)(&As[cur][kk][64 + ty * 4]);
            ulonglong2 bl = *(const ulonglong2*)(&Bs[cur][kk][tx * 4]);
            ulonglong2 bh = *(const ulonglong2*)(&Bs[cur][kk][64 + tx * 4]);
            u64 b2[4] = { bl.x, bl.y, bh.x, bh.y };
            float af[8] = { afl.x, afl.y, afl.z, afl.w,
                            afh.x, afh.y, afh.z, afh.w };
#pragma unroll
            for (int i = 0; i < 8; i++) {
                u64 a2 = pk2d(af[i]);
#pragma unroll
                for (int j = 0; j < 4; j++) fma2(acc[i][j], a2, b2[j]);
            }
        }
        if (more) {
            int nxt = cur ^ 1;
            As[nxt][lc + 0][lr] = na0.x; As[nxt][lc + 1][lr] = na0.y;
            As[nxt][lc + 2][lr] = na0.z; As[nxt][lc + 3][lr] = na0.w;
            As[nxt][lc + 4][lr] = na1.x; As[nxt][lc + 5][lr] = na1.y;
            As[nxt][lc + 6][lr] = na1.z; As[nxt][lc + 7][lr] = na1.w;
            Bs[nxt][lc + 0][lr] = nb0.x; Bs[nxt][lc + 1][lr] = nb0.y;
            Bs[nxt][lc + 2][lr] = nb0.z; Bs[nxt][lc + 3][lr] = nb0.w;
            Bs[nxt][lc + 4][lr] = nb1.x; Bs[nxt][lc + 5][lr] = nb1.y;
            Bs[nxt][lc + 6][lr] = nb1.z; Bs[nxt][lc + 7][lr] = nb1.w;
            __syncthreads();
            cur = nxt;
        }
    }

    // Epilogue
#pragma unroll
    for (int i = 0; i < 8; i++) {
        int m = bm * 128 + ((i < 4) ? (ty * 4 + i) : (64 + ty * 4 + (i - 4)));
        if (EPI == 0) {
            int b = m >> 11, t = m & 2047;
#pragma unroll
            for (int jj = 0; jj < 4; jj++) {
                float x, y; up2(acc[i][jj], x, y);
                int n0 = bn * 128 + ((jj < 2) ? (tx * 4 + 2 * jj)
                                             : (64 + tx * 4 + 2 * (jj - 2)));
                float vv[2] = { x, y };
#pragma unroll
                for (int e = 0; e < 2; e++) {
                    int n = n0 + e;
                    int which = n >> 10;
                    int c = n & 1023;
                    int h = c >> 6, d = c & 63;
                    size_t idx = (((size_t)(b * HH + h)) * TT + t) * DD + d;
                    if (which == 0)      g_Q[idx] = vv[e] * 0.125f;
                    else if (which == 1) g_K[idx] = vv[e];
                    else                 g_V[idx] = vv[e];
                }
            }
        } else {
            float x0, y0, x1, y1;
            up2(acc[i][0], x0, y0); up2(acc[i][1], x1, y1);
            float4 v = make_float4(x0, y0, x1, y1);
            *(float4*)&Cout[(size_t)m * Ndim + bn * 128 + tx * 4] = v;
            up2(acc[i][2], x0, y0); up2(acc[i][3], x1, y1);
            v = make_float4(x0, y0, x1, y1);
            *(float4*)&Cout[(size_t)m * Ndim + bn * 128 + 64 + tx * 4] = v;
        }
    }
}

// ---------------------------------------------------------------------------
// Flash attention (causal), fp32 with packed f32x2 math.
// One block per (q-tile 64, head, batch). 256 threads as 16x16:
// each thread owns a 4(rows) x 4(cols/dims) micro-tile.
// smem tiles stored d-major (transposed) so reads are broadcast + float4.
// ---------------------------------------------------------------------------
#define ATS 68                     // smem row stride (floats), float4-aligned
#define ATT_SMEM_FLOATS (4 * 64 * ATS)

__global__ __launch_bounds__(256)
void flash_attn_kernel()
{
    extern __shared__ float sm[];
    float* Qt = sm;                 // [64][68]  Qt[d][r]
    float* Kt = sm + 64 * ATS;      // [64][68]  Kt[d][c]
    float* Vs = sm + 2 * 64 * ATS;  // [64][68]  Vs[c][d]
    float* Pt = sm + 3 * 64 * ATS;  // [64][68]  Pt[c][r]

    const int b = blockIdx.z, h = blockIdx.y, qb = blockIdx.x;
    const int tid = threadIdx.x;
    const size_t hb = ((size_t)(b * HH + h)) * TT * DD;
    const float* Qg = g_Q + hb + (size_t)qb * 64 * DD;
    const float* Kg = g_K + hb;
    const float* Vg = g_V + hb;

    // Transposed-load mapping: one column per lane -> conflict-free STS
    const int lcol  = tid & 63;            // row index in gmem (r or c)
    const int dbase = (tid >> 6) * 16;     // 16 d's per thread

    // Q tile -> Qt[d][r]
#pragma unroll
    for (int u = 0; u < 4; u++) {
        int d4 = dbase + 4 * u;
        float4 q4 = *(const float4*)&Qg[lcol * 64 + d4];
        Qt[(d4 + 0) * ATS + lcol] = q4.x;
        Qt[(d4 + 1) * ATS + lcol] = q4.y;
        Qt[(d4 + 2) * ATS + lcol] = q4.z;
        Qt[(d4 + 3) * ATS + lcol] = q4.w;
    }

    const int tx = tid & 15, ty = tid >> 4;
    const int r0 = ty * 4;     // rows r0..r0+3
    const int c0 = tx * 4;     // cols (or dims) c0..c0+3

    float m_i[4], l_i[4];
    u64 o2[4][2];
#pragma unroll
    for (int i = 0; i < 4; i++) {
        m_i[i] = -INFINITY; l_i[i] = 0.f;
        o2[i][0] = 0ull; o2[i][1] = 0ull;
    }

    for (int j = 0; j <= qb; j++) {
        __syncthreads();    // previous iteration done with Kt/Vs/Pt
        const float* Kj = Kg + (size_t)j * 64 * DD;
        const float* Vj = Vg + (size_t)j * 64 * DD;

        // K tile -> Kt[d][c] (conflict-free transposed stores)
#pragma unroll
        for (int u = 0; u < 4; u++) {
            int d4 = dbase + 4 * u;
            float4 k4 = *(const float4*)&Kj[lcol * 64 + d4];
            Kt[(d4 + 0) * ATS + lcol] = k4.x;
            Kt[(d4 + 1) * ATS + lcol] = k4.y;
            Kt[(d4 + 2) * ATS + lcol] = k4.z;
            Kt[(d4 + 3) * ATS + lcol] = k4.w;
        }
        // V tile -> Vs[c][d] straight copy
#pragma unroll
        for (int u = 0; u < 4; u++) {
            int idx = tid + u * 256;
            int rr = idx >> 4, c4 = (idx & 15) * 4;
            *(float4*)&Vs[rr * ATS + c4] = *(const float4*)&Vj[rr * 64 + c4];
        }
        __syncthreads();

        // S = Q K^T : 4x4 micro-tile in packed pairs
        u64 s2[4][2];
#pragma unroll
        for (int i = 0; i < 4; i++) { s2[i][0] = 0ull; s2[i][1] = 0ull; }
#pragma unroll 16
        for (int d = 0; d < 64; d++) {
            float4 a4 = *(const float4*)&Qt[d * ATS + r0];
            ulonglong2 k2 = *(const ulonglong2*)&Kt[d * ATS + c0];
            u64 aa;
            aa = pk2d(a4.x); fma2(s2[0][0], aa, k2.x); fma2(s2[0][1], aa, k2.y);
            aa = pk2d(a4.y); fma2(s2[1][0], aa, k2.x); fma2(s2[1][1], aa, k2.y);
            aa = pk2d(a4.z); fma2(s2[2][0], aa, k2.x); fma2(s2[2][1], aa, k2.y);
            aa = pk2d(a4.w); fma2(s2[3][0], aa, k2.x); fma2(s2[3][1], aa, k2.y);
        }

        // unpack
        float s[4][4];
#pragma unroll
        for (int i = 0; i < 4; i++) {
            up2(s2[i][0], s[i][0], s[i][1]);
            up2(s2[i][1], s[i][2], s[i][3]);
        }
        // causal mask on diagonal block
        if (j == qb) {
#pragma unroll
            for (int i = 0; i < 4; i++)
#pragma unroll
                for (int cc = 0; cc < 4; cc++)
                    if (c0 + cc > r0 + i) s[i][cc] = -INFINITY;
        }
        // online softmax (per row, reduce over the 16 tx lanes)
#pragma unroll
        for (int i = 0; i < 4; i++) {
            float mloc = fmaxf(fmaxf(s[i][0], s[i][1]), fmaxf(s[i][2], s[i][3]));
            mloc = fmaxf(mloc, __shfl_xor_sync(0xffffffffu, mloc, 1));
            mloc = fmaxf(mloc, __shfl_xor_sync(0xffffffffu, mloc, 2));
            mloc = fmaxf(mloc, __shfl_xor_sync(0xffffffffu, mloc, 4));
            mloc = fmaxf(mloc, __shfl_xor_sync(0xffffffffu, mloc, 8));
            float mnew = fmaxf(m_i[i], mloc);
            float al = __expf(m_i[i] - mnew);
            float ps = 0.f;
#pragma unroll
            for (int cc = 0; cc < 4; cc++) {
                float p = __expf(s[i][cc] - mnew);
                s[i][cc] = p;
                ps += p;
            }
            ps += __shfl_xor_sync(0xffffffffu, ps, 1);
            ps += __shfl_xor_sync(0xffffffffu, ps, 2);
            ps += __shfl_xor_sync(0xffffffffu, ps, 4);
            ps += __shfl_xor_sync(0xffffffffu, ps, 8);
            l_i[i] = al * l_i[i] + ps;
            m_i[i] = mnew;
            u64 al2 = pk2d(al);
            mul2(o2[i][0], al2);
            mul2(o2[i][1], al2);
        }
        // store P transposed: Pt[c][r]
#pragma unroll
        for (int cc = 0; cc < 4; cc++) {
            float4 p4 = make_float4(s[0][cc], s[1][cc], s[2][cc], s[3][cc]);
            *(float4*)&Pt[(c0 + cc) * ATS + r0] = p4;
        }
        __syncthreads();

        // O += P V : rows r0.., dims c0..
#pragma unroll 16
        for (int c = 0; c < 64; c++) {
            float4 p4 = *(const float4*)&Pt[c * ATS + r0];
            ulonglong2 v2 = *(const ulonglong2*)&Vs[c * ATS + c0];
            u64 aa;
            aa = pk2d(p4.x); fma2(o2[0][0], aa, v2.x); fma2(o2[0][1], aa, v2.y);
            aa = pk2d(p4.y); fma2(o2[1][0], aa, v2.x); fma2(o2[1][1], aa, v2.y);
            aa = pk2d(p4.z); fma2(o2[2][0], aa, v2.x); fma2(o2[2][1], aa, v2.y);
            aa = pk2d(p4.w); fma2(o2[3][0], aa, v2.x); fma2(o2[3][1], aa, v2.y);
        }
    }

    // epilogue: normalize and write to g_O [B,T,C]
#pragma unroll
    for (int i = 0; i < 4; i++) {
        float inv = 1.f / l_i[i];
        float x0, y0, x1, y1;
        up2(o2[i][0], x0, y0);
        up2(o2[i][1], x1, y1);
        float4 v = make_float4(x0 * inv, y0 * inv, x1 * inv, y1 * inv);
        int r = qb * 64 + r0 + i;
        *(float4*)&g_O[((size_t)(b * TT + r)) * CC + h * DD + c0] = v;
    }
}

// ---------------------------------------------------------------------------
extern "C" void kernel_launch(void* const* d_in, const int* in_sizes, int n_in,
                              void* d_out, int out_size)
{
    const float* x     = (const float*)d_in[0];
    // d_in[1] = mask (bool) — causal, applied analytically
    const float* w_qkv = (const float*)d_in[2];
    const float* w_out = (const float*)d_in[3];
    float* out = (float*)d_out;

    // 1) QKV projection -> g_Q (scaled), g_K, g_V
    {
        dim3 grid(NQKV / 128, MTOT / 128);   // (24, 64)
        sgemm_nt<0><<<grid, 256>>>(x, w_qkv, nullptr, CC, NQKV);
    }
    // 2) causal flash attention -> g_O
    {
        cudaFuncSetAttribute(flash_attn_kernel,
                             cudaFuncAttributeMaxDynamicSharedMemorySize,
                             ATT_SMEM_FLOATS * (int)sizeof(float));
        dim3 grid(TT / 64, HH, BB);          // (32, 16, 4)
        flash_attn_kernel<<<grid, 256, ATT_SMEM_FLOATS * sizeof(float)>>>();
    }
    // 3) output projection -> d_out
    {
        dim3 grid(CC / 128, MTOT / 128);     // (8, 64)
        sgemm_nt<1><<<grid, 256>>>(nullptr, w_out, out, CC, CC);
    }
}